// round 13
// baseline (speedup 1.0000x reference)
#include <cuda_runtime.h>
#include <cuda_bf16.h>
#include <math.h>
#include <stdint.h>

typedef __nv_bfloat16 bf16;

#define BATCH 2048
#define TTL   30
#define IN_DIM 60
#define HDIM  512
#define G4    2048
#define NL    5
#define OUTD  23
#define TPTS  90

// ============================ static scratch ============================
__device__ float g_z    [BATCH * 2 * HDIM];
__device__ float g_biasp[NL * G4];
__device__ bf16  g_x30h[BATCH * 64],  g_x30l[BATCH * 64];
__device__ bf16  g_mih [BATCH * 64],  g_mil [BATCH * 64];
__device__ bf16  g_wi0h[G4 * 64],     g_wi0l[G4 * 64];
__device__ bf16  g_wirh[4 * G4 * HDIM], g_wirl[4 * G4 * HDIM];
__device__ bf16  g_whhh[5 * G4 * HDIM], g_whhl[5 * G4 * HDIM];
__device__ bf16  g_h0h [5 * BATCH * HDIM], g_h0l[5 * BATCH * HDIM];
__device__ bf16  g_mw1h[HDIM * 64],   g_mw1l[HDIM * 64];
__device__ bf16  g_mw2h[HDIM * HDIM], g_mw2l[HDIM * HDIM];
__device__ bf16  g_r1ah[2 * HDIM * HDIM], g_r1al[2 * HDIM * HDIM];
__device__ bf16  g_r1bh[2 * HDIM * HDIM], g_r1bl[2 * HDIM * HDIM];
__device__ bf16  g_xAh [BATCH * HDIM], g_xAl[BATCH * HDIM];
__device__ bf16  g_xBh [BATCH * HDIM], g_xBl[BATCH * HDIM];
__device__ bf16  g_m1h [BATCH * HDIM], g_m1l[BATCH * HDIM];
__device__ bf16  g_m2h [BATCH * HDIM], g_m2l[BATCH * HDIM];

// ============================ helpers ============================
static __device__ __forceinline__ uint32_t smem_u32(const void* p) {
    uint32_t a;
    asm("{ .reg .u64 t; cvta.to.shared.u64 t, %1; cvt.u32.u64 %0, t; }" : "=r"(a) : "l"(p));
    return a;
}
static __device__ __forceinline__ void cpa16(uint32_t d, const void* s) {
    asm volatile("cp.async.cg.shared.global [%0], [%1], 16;" :: "r"(d), "l"(s));
}
static __device__ __forceinline__ void cp_commit() {
    asm volatile("cp.async.commit_group;" ::: "memory");
}
static __device__ __forceinline__ void cp_wait0() {
    asm volatile("cp.async.wait_group 0;" ::: "memory");
}
static __device__ __forceinline__ void cp_wait1() {
    asm volatile("cp.async.wait_group 1;" ::: "memory");
}
static __device__ __forceinline__ void ldsm4(uint32_t* r, uint32_t a) {
    asm volatile("ldmatrix.sync.aligned.m8n8.x4.shared.b16 {%0,%1,%2,%3}, [%4];"
                 : "=r"(r[0]), "=r"(r[1]), "=r"(r[2]), "=r"(r[3]) : "r"(a));
}
static __device__ __forceinline__ void mma16816(float* c, const uint32_t* a, const uint32_t* b) {
    asm volatile("mma.sync.aligned.m16n8k16.row.col.f32.bf16.bf16.f32 "
                 "{%0,%1,%2,%3}, {%4,%5,%6,%7}, {%8,%9}, {%0,%1,%2,%3};"
                 : "+f"(c[0]), "+f"(c[1]), "+f"(c[2]), "+f"(c[3])
                 : "r"(a[0]), "r"(a[1]), "r"(a[2]), "r"(a[3]), "r"(b[0]), "r"(b[1]));
}
static __device__ __forceinline__ float sigf(float x) { return 1.f / (1.f + expf(-x)); }

// ============================ GEMM kernel ============================
// CTA tile 128x128, warps 4(M)x2(N), warp tile 32x64, BK=32, 80B row stride,
// 3-stage cp.async, ONE __syncthreads per chunk.  (Best empirical config: R9.)
struct Seg { const bf16* A; const bf16* B; int K; };
struct GArgs {
    Seg s[6]; int nseg;
    const float* bias1;
    const float* c0;      // op==3 (fused lstm cell)
    float* tso;           // op==3 optional float x output
    float* Cf; bf16* Ch; bf16* Cl;
    int ldc; int op;  // 0 none, 1 relu, 2 tanh, 3 lstm-cell (interleaved gates)
};
#define STAGE_B 20480u
#define GEMM_SMEM (20480 * 3)

__global__ __launch_bounds__(256, 2)
void gemm_tc(GArgs args)
{
    extern __shared__ __align__(256) char smem[];
    const uint32_t sb = smem_u32(smem);
    const int tid = threadIdx.x;
    const int wid = tid >> 5;
    const int lane = tid & 31;
    const int bM = blockIdx.y * 128;
    const int bN = blockIdx.x * 128;

    int segBase[7];
    segBase[0] = 0;
#pragma unroll
    for (int i = 0; i < 6; i++)
        segBase[i + 1] = segBase[i] + ((i < args.nseg) ? (args.s[i].K >> 5) : 0);
    const int nch = segBase[6];

    const int wm = (wid >> 1) * 32;
    const int wn = (wid & 1) * 64;

    float ac[2][8][4];
#pragma unroll
    for (int mt = 0; mt < 2; mt++)
#pragma unroll
        for (int nt = 0; nt < 8; nt++)
#pragma unroll
            for (int i = 0; i < 4; i++) ac[mt][nt][i] = 0.f;

    auto slotOf = [&](int cc) -> uint32_t {
        return sb + (uint32_t)(cc % 3) * STAGE_B;
    };
    auto loadChunk = [&](int cc) {
        int s = 0;
#pragma unroll
        for (int i = 0; i < 5; i++) if (cc >= segBase[i + 1]) s = i + 1;
        const bf16* A = args.s[s].A;
        const bf16* B = args.s[s].B;
        const int K = args.s[s].K;
        const int k0 = (cc - segBase[s]) * 32;
        uint32_t st = slotOf(cc);
#pragma unroll
        for (int i = 0; i < 2; i++) {
            int ch = tid + i * 256;
            int row = ch >> 2, cb = ch & 3;
            cpa16(st + (uint32_t)(row * 80 + cb * 16),
                  A + (size_t)(bM + row) * K + k0 + cb * 8);
        }
#pragma unroll
        for (int i = 0; i < 2; i++) {
            int ch = tid + i * 256;
            int row = ch >> 2, cb = ch & 3;
            cpa16(st + 10240u + (uint32_t)(row * 80 + cb * 16),
                  B + (size_t)(bN + row) * K + k0 + cb * 8);
        }
    };

    loadChunk(0); cp_commit();
    if (nch > 1) { loadChunk(1); cp_commit(); }
    for (int cc = 0; cc < nch; cc++) {
        if (cc < nch - 1) cp_wait1(); else cp_wait0();
        __syncthreads();
        if (cc + 2 < nch) { loadChunk(cc + 2); cp_commit(); }
        uint32_t stA = slotOf(cc);
        uint32_t stB = stA + 10240u;
#pragma unroll
        for (int kk = 0; kk < 32; kk += 16) {
            uint32_t af[2][4], bfr[4][4];
#pragma unroll
            for (int mt = 0; mt < 2; mt++)
                ldsm4(af[mt], stA + (uint32_t)((wm + mt * 16 + (lane & 15)) * 80
                                               + (kk + (lane >> 4) * 8) * 2));
#pragma unroll
            for (int p = 0; p < 4; p++)
                ldsm4(bfr[p], stB + (uint32_t)((wn + p * 16 + (lane & 7) + ((lane >> 4) & 1) * 8) * 80
                                               + (kk + ((lane >> 3) & 1) * 8) * 2));
#pragma unroll
            for (int mt = 0; mt < 2; mt++)
#pragma unroll
                for (int nt = 0; nt < 8; nt++)
                    mma16816(ac[mt][nt], af[mt], &bfr[nt >> 1][(nt & 1) * 2]);
        }
    }

    if (args.op == 3) {
        // fused LSTM cell: interleaved gate columns 4h+{i,f,g,o}
#pragma unroll
        for (int mt = 0; mt < 2; mt++)
#pragma unroll
            for (int nt = 0; nt < 8; nt++) {
                int row = bM + wm + mt * 16 + (lane >> 2);
                int col = bN + wn + nt * 8 + 2 * (lane & 3);
                float v0 = ac[mt][nt][0] + args.bias1[col];
                float v1 = ac[mt][nt][1] + args.bias1[col + 1];
                float v2 = ac[mt][nt][2] + args.bias1[col];
                float v3 = ac[mt][nt][3] + args.bias1[col + 1];
                float p0 = __shfl_xor_sync(0xffffffffu, v0, 1);
                float p1 = __shfl_xor_sync(0xffffffffu, v1, 1);
                float p2 = __shfl_xor_sync(0xffffffffu, v2, 1);
                float p3 = __shfl_xor_sync(0xffffffffu, v3, 1);
                if (!(lane & 1)) {
                    int h = col >> 2;
                    float c1 = args.c0[(size_t)row * HDIM + h];
                    float c2 = args.c0[(size_t)(row + 8) * HDIM + h];
                    float cc1 = sigf(v1) * c1 + sigf(v0) * tanhf(p0);
                    float x1 = sigf(p1) * tanhf(cc1);
                    float cc2 = sigf(v3) * c2 + sigf(v2) * tanhf(p2);
                    float x2 = sigf(p3) * tanhf(cc2);
                    bf16 h1 = __float2bfloat16(x1);
                    bf16 h2 = __float2bfloat16(x2);
                    size_t i1 = (size_t)row * HDIM + h;
                    size_t i2 = (size_t)(row + 8) * HDIM + h;
                    args.Ch[i1] = h1;
                    args.Cl[i1] = __float2bfloat16(x1 - __bfloat162float(h1));
                    args.Ch[i2] = h2;
                    args.Cl[i2] = __float2bfloat16(x2 - __bfloat162float(h2));
                    if (args.tso) { args.tso[i1] = x1; args.tso[i2] = x2; }
                }
            }
        return;
    }

    auto storePair = [&](int row, int col, float v0, float v1) {
        if (args.bias1) { v0 += args.bias1[col]; v1 += args.bias1[col + 1]; }
        if (args.op == 1)      { v0 = fmaxf(v0, 0.f); v1 = fmaxf(v1, 0.f); }
        else if (args.op == 2) { v0 = tanhf(v0); v1 = tanhf(v1); }
        size_t base = (size_t)row * args.ldc + col;
        if (args.Cf)
            *reinterpret_cast<float2*>(args.Cf + base) = make_float2(v0, v1);
        if (args.Ch) {
            bf16 h0 = __float2bfloat16(v0), h1 = __float2bfloat16(v1);
            bf16 l0 = __float2bfloat16(v0 - __bfloat162float(h0));
            bf16 l1 = __float2bfloat16(v1 - __bfloat162float(h1));
            *reinterpret_cast<uint32_t*>(args.Ch + base) =
                (uint32_t)__bfloat16_as_ushort(h0) | ((uint32_t)__bfloat16_as_ushort(h1) << 16);
            *reinterpret_cast<uint32_t*>(args.Cl + base) =
                (uint32_t)__bfloat16_as_ushort(l0) | ((uint32_t)__bfloat16_as_ushort(l1) << 16);
        }
    };
#pragma unroll
    for (int mt = 0; mt < 2; mt++)
#pragma unroll
        for (int nt = 0; nt < 8; nt++) {
            int row = bM + wm + mt * 16 + (lane >> 2);
            int col = bN + wn + nt * 8 + 2 * (lane & 3);
            storePair(row,     col, ac[mt][nt][0], ac[mt][nt][1]);
            storePair(row + 8, col, ac[mt][nt][2], ac[mt][nt][3]);
        }
}

// ============================ conversion ============================
__global__ void conv_hl(const float* __restrict__ src, int rows, int Ks, int ld, int Kd,
                        bf16* __restrict__ h, bf16* __restrict__ l,
                        const float* __restrict__ divr, int permBlock)
{
    int idx = blockIdx.x * blockDim.x + threadIdx.x;
    if (idx >= rows * Kd) return;
    int r = idx / Kd, k = idx - r * Kd;
    int sr = r;
    if (permBlock) {
        int blk = r / permBlock, rr = r - blk * permBlock;
        sr = blk * permBlock + (rr & 3) * 512 + (rr >> 2);
    }
    float v = (k < Ks) ? src[(size_t)sr * ld + k] : 0.f;
    if (divr) v /= divr[r];
    bf16 hb = __float2bfloat16(v);
    h[idx] = hb;
    l[idx] = __float2bfloat16(v - __bfloat162float(hb));
}

__global__ void biasp_kernel(const float* __restrict__ b_ih, const float* __restrict__ b_hh,
                             float* __restrict__ bp)
{
    int idx = blockIdx.x * blockDim.x + threadIdx.x;
    if (idx >= NL * G4) return;
    int l = idx >> 11, rr = idx & 2047;
    int sr = (rr & 3) * 512 + (rr >> 2);
    bp[idx] = b_ih[l * G4 + sr] + b_hh[l * G4 + sr];
}

__global__ void raw_dnn_kernel(const float* __restrict__ z, const float* __restrict__ W2,
                               const float* __restrict__ b2, const float* __restrict__ rng,
                               const void* __restrict__ scale_ptr,
                               float* __restrict__ raw_out, float* __restrict__ dnn_out)
{
    __shared__ float zs[2 * HDIM];
    int b = blockIdx.x;
    const float* zr = z + (size_t)b * 2 * HDIM;
    for (int i = threadIdx.x; i < 2 * HDIM; i += blockDim.x) zs[i] = zr[i];
    __syncthreads();
    int warp = threadIdx.x >> 5, lane = threadIdx.x & 31;
    int bits = *(const int*)scale_ptr;
    float f = __int_as_float(bits);
    float af = fabsf(f);
    float s = (af >= 1e-30f && af <= 1e30f) ? f : (float)bits;
    for (int o = warp; o < OUTD; o += 8) {
        const float* w = W2 + (size_t)o * 2 * HDIM;
        float acc = 0.f;
        for (int k = lane; k < 2 * HDIM; k += 32) acc += zs[k] * w[k];
#pragma unroll
        for (int off = 16; off; off >>= 1) acc += __shfl_xor_sync(0xffffffffu, acc, off);
        if (lane == 0) {
            float r = acc + b2[o];
            raw_out[(size_t)b * OUTD + o] = r;
            dnn_out[(size_t)b * OUTD + o] = (1.f / (1.f + expf(-r * s))) * rng[o];
        }
    }
}

// ============================ ODE ============================
#define LN2D 0.6931471805599453
#define C_RI  ((float)(LN2D / 5.0))
#define C_RD  ((float)(LN2D / 2.0))
#define C_RRI ((float)(LN2D / 10.0))
#define C_RRH ((float)(LN2D / 15.0))
#define C_RRV ((float)(LN2D / 10.0))
#define TWO_OVER_PI 0.6366197723675814f
#define HALF_PI     1.5707963267948966f

// fast atan: degree-11 odd minimax on [0,1] + reciprocal range reduction (~1e-5 abs err)
static __device__ __forceinline__ float fatan(float x) {
    float ax = fabsf(x);
    bool big = ax > 1.0f;
    float z = big ? __fdividef(1.0f, ax) : ax;
    float z2 = z * z;
    float p = -0.0117212f;
    p = fmaf(p, z2,  0.05265332f);
    p = fmaf(p, z2, -0.11643287f);
    p = fmaf(p, z2,  0.19354346f);
    p = fmaf(p, z2, -0.33262347f);
    p = fmaf(p, z2,  0.99997726f);
    float r = z * p;
    r = big ? (HALF_PI - r) : r;
    return copysignf(r, x);
}

__device__ __forceinline__ void covid_deriv(const float y[16], float gam, float pdt,
                                            float aN, float r_dth, float d[16])
{
    float S = y[0], E = y[1], I = y[2];
    float AR = y[3], DHR = y[4], DQR = y[5], AD = y[6], DHD = y[7], DQD = y[8];
    float DVR = y[12], DVD = y[13];
    float inf = aN * gam * S * I;
    float det = C_RD * I;
    float d1m = det * (1.f - pdt);
    float dp  = det * pdt;
    d[0] = -inf;
    d[1] = inf - C_RI * E;
    d[2] = C_RI * E - det;
    d[3] = d1m * 0.8f - C_RRI * AR;
    d[4] = d1m * 0.03f - C_RRH * DHR;
    d[5] = d1m * 0.17f - C_RRI * DQR;
    d[6] = dp * 0.8f - r_dth * AD;
    d[7] = dp * 0.03f - r_dth * DHD;
    d[8] = dp * 0.17f - r_dth * DQD;
    d[9] = C_RRI * (AR + DQR) + C_RRH * DHR;
    d[10] = r_dth * (AD + DQD + DHD);
    d[11] = det * 0.03f;
    d[12] = d1m * 0.0075f - C_RRV * DVR;
    d[13] = dp * 0.0075f - r_dth * DVD;
    d[14] = r_dth * (DHD + DQD);
    d[15] = det * 0.2f;
}
__device__ __forceinline__ float gam_f(float t, float days, float rs20,
                                       float jump, float t_jump, float inv2s2)
{
    float dtj = t - t_jump;
    return TWO_OVER_PI * fatan((days - t) * rs20) + 1.0f + jump * __expf(-dtj * dtj * inv2s2);
}
__device__ __forceinline__ float pdt_f(float t, float pc, float rdd20)
{
    return pc * (fatan(-t * rdd20) + HALF_PI) + 0.001f;
}

__global__ void ode_kernel(const float* __restrict__ pop, const float* __restrict__ ccn,
                           const float* __restrict__ mort, const float* __restrict__ dnn,
                           float* __restrict__ sol)
{
    int b = blockIdx.x * blockDim.x + threadIdx.x;
    if (b >= BATCH) return;
    const float* dn = dnn + (size_t)b * OUTD;
    float alpha = dn[11], days = dn[12], r_s = dn[13], r_dth = dn[14], p_dth = dn[15];
    float r_dthdecay = dn[16], k1 = dn[17], k2 = dn[18], jump = dn[19];
    float t_jump = dn[20], stdn = dn[21];

    float N = pop[b];
    float PopI = ccn[b];
    float PopD = floorf(mort[b] * PopI);
    float R0 = (PopI - PopD > 5.0f * PopD) ? 5.0f * PopD : 0.0f;
    float PopCI = PopI - PopD - R0;
    float ciPD = PopCI / 0.2f;
    float omp = 1.0f - p_dth;

    float y[16];
    y[0] = N - ciPD * (k1 + k2) - R0 / 0.2f - PopD / 0.2f;
    y[1] = ciPD * k1;  y[2] = ciPD * k2;
    y[3] = (ciPD - PopCI) * omp;
    y[4] = PopCI * 0.15f * omp;
    y[5] = PopCI * 0.85f * omp;
    y[6] = (ciPD - PopCI) * p_dth;
    y[7] = PopCI * 0.15f * p_dth;
    y[8] = PopCI * 0.85f * p_dth;
    y[9] = R0 / 0.2f;  y[10] = PopD / 0.2f;
    y[11] = PopCI * 0.15f;
    y[12] = PopCI * 0.0375f * omp;
    y[13] = PopCI * 0.0375f * p_dth;
    y[14] = PopD;  y[15] = PopI;

    float* srow = sol + (size_t)b * TPTS * 16;
#pragma unroll
    for (int i = 0; i < 16; i++) srow[i] = y[i];

    float aN = alpha / N;
    float rs20 = r_s * 0.05f;
    float rdd20 = r_dthdecay * 0.05f;
    float inv2s2 = 1.0f / (2.0f * stdn * stdn);
    float pc = TWO_OVER_PI * (p_dth - 0.001f);

    for (int seg = 0; seg < TPTS - 1; seg++) {
        float t0 = (float)seg;
        for (int j = 0; j < 10; j++) {
            float t = t0 + (float)j * 0.1f;
            float g1 = gam_f(t, days, rs20, jump, t_jump, inv2s2);
            float g2 = gam_f(t + 0.05f, days, rs20, jump, t_jump, inv2s2);
            float g3 = gam_f(t + 0.1f, days, rs20, jump, t_jump, inv2s2);
            float p1 = pdt_f(t, pc, rdd20);
            float p2 = pdt_f(t + 0.05f, pc, rdd20);
            float p3 = pdt_f(t + 0.1f, pc, rdd20);
            float k[16], acc[16], yy[16];
            covid_deriv(y, g1, p1, aN, r_dth, k);
#pragma unroll
            for (int i = 0; i < 16; i++) { acc[i] = k[i]; yy[i] = y[i] + 0.05f * k[i]; }
            covid_deriv(yy, g2, p2, aN, r_dth, k);
#pragma unroll
            for (int i = 0; i < 16; i++) { acc[i] += 2.f * k[i]; yy[i] = y[i] + 0.05f * k[i]; }
            covid_deriv(yy, g2, p2, aN, r_dth, k);
#pragma unroll
            for (int i = 0; i < 16; i++) { acc[i] += 2.f * k[i]; yy[i] = y[i] + 0.1f * k[i]; }
            covid_deriv(yy, g3, p3, aN, r_dth, k);
#pragma unroll
            for (int i = 0; i < 16; i++) y[i] += (0.1f / 6.0f) * (acc[i] + k[i]);
        }
        float* o = srow + (size_t)(seg + 1) * 16;
#pragma unroll
        for (int i = 0; i < 16; i++) o[i] = y[i];
    }
}

// ============================ launch ============================
static void* sym(const void* s) { void* p; cudaGetSymbolAddress(&p, s); return p; }

extern "C" void kernel_launch(void* const* d_in, const int* in_sizes, int n_in,
                              void* d_out, int out_size)
{
    const float* mi    = (const float*)d_in[0];
    const float* pop   = (const float*)d_in[1];
    const float* ccn   = (const float*)d_in[2];
    const float* mort  = (const float*)d_in[3];
    const float* h0    = (const float*)d_in[4];
    const float* c0    = (const float*)d_in[5];
    const float* W_ih0 = (const float*)d_in[6];
    const float* W_ihR = (const float*)d_in[7];
    const float* W_hh  = (const float*)d_in[8];
    const float* b_ih  = (const float*)d_in[9];
    const float* b_hh  = (const float*)d_in[10];
    const float* mW1   = (const float*)d_in[11];
    const float* mb1   = (const float*)d_in[12];
    const float* mW2   = (const float*)d_in[13];
    const float* mb2   = (const float*)d_in[14];
    const float* rW1   = (const float*)d_in[15];
    const float* rb1   = (const float*)d_in[16];
    const float* rW2   = (const float*)d_in[17];
    const float* rb2   = (const float*)d_in[18];
    const float* rng   = (const float*)d_in[19];
    const void*  scl   = d_in[20];

    float* out = (float*)d_out;
    float* sol = out;
    float* dnn = out + (size_t)BATCH * TPTS * 16;
    float* ts  = dnn + (size_t)BATCH * OUTD;
    float* raw = ts  + (size_t)BATCH * HDIM;

    float* zb    = (float*)sym(g_z);
    float* biasp = (float*)sym(g_biasp);
    bf16 *x30h = (bf16*)sym(g_x30h), *x30l = (bf16*)sym(g_x30l);
    bf16 *mih  = (bf16*)sym(g_mih),  *mil  = (bf16*)sym(g_mil);
    bf16 *wi0h = (bf16*)sym(g_wi0h), *wi0l = (bf16*)sym(g_wi0l);
    bf16 *wirh = (bf16*)sym(g_wirh), *wirl = (bf16*)sym(g_wirl);
    bf16 *whhh = (bf16*)sym(g_whhh), *whhl = (bf16*)sym(g_whhl);
    bf16 *h0h  = (bf16*)sym(g_h0h),  *h0l  = (bf16*)sym(g_h0l);
    bf16 *mw1h = (bf16*)sym(g_mw1h), *mw1l = (bf16*)sym(g_mw1l);
    bf16 *mw2h = (bf16*)sym(g_mw2h), *mw2l = (bf16*)sym(g_mw2l);
    bf16 *r1ah = (bf16*)sym(g_r1ah), *r1al = (bf16*)sym(g_r1al);
    bf16 *r1bh = (bf16*)sym(g_r1bh), *r1bl = (bf16*)sym(g_r1bl);
    bf16 *xAh  = (bf16*)sym(g_xAh),  *xAl  = (bf16*)sym(g_xAl);
    bf16 *xBh  = (bf16*)sym(g_xBh),  *xBl  = (bf16*)sym(g_xBl);
    bf16 *m1h  = (bf16*)sym(g_m1h),  *m1l  = (bf16*)sym(g_m1l);
    bf16 *m2h  = (bf16*)sym(g_m2h),  *m2l  = (bf16*)sym(g_m2l);

    static cudaStream_t s1 = nullptr;
    static cudaEvent_t  evF = nullptr, evJ = nullptr, evC = nullptr;
    if (!s1) {
        cudaStreamCreateWithFlags(&s1, cudaStreamNonBlocking);
        cudaEventCreateWithFlags(&evF, cudaEventDisableTiming);
        cudaEventCreateWithFlags(&evJ, cudaEventDisableTiming);
        cudaEventCreateWithFlags(&evC, cudaEventDisableTiming);
        cudaFuncSetAttribute(gemm_tc, cudaFuncAttributeMaxDynamicSharedMemorySize, GEMM_SMEM);
    }

    auto CV = [&](cudaStream_t st, const float* s, int rows, int Ks, int ld, int Kd,
                  bf16* h, bf16* l, const float* dv, int perm) {
        int n = rows * Kd;
        conv_hl<<<(n + 255) / 256, 256, 0, st>>>(s, rows, Ks, ld, Kd, h, l, dv, perm);
    };
    auto GL = [&](cudaStream_t st, dim3 grid, Seg* sg, int ns, const float* b1,
                  const float* c0p, float* tso,
                  float* Cf, bf16* Ch, bf16* Cl, int ldc, int op) {
        GArgs a = {};
        for (int i = 0; i < ns; i++) a.s[i] = sg[i];
        a.nseg = ns; a.bias1 = b1; a.c0 = c0p; a.tso = tso;
        a.Cf = Cf; a.Ch = Ch; a.Cl = Cl; a.ldc = ldc; a.op = op;
        gemm_tc<<<grid, 256, GEMM_SMEM, st>>>(a);
    };

    // fork s1 from capture origin
    cudaEventRecord(evF, 0);
    cudaStreamWaitEvent(s1, evF, 0);

    // ---- default stream: ONLY layer-0-critical conversions ----
    CV(0, mi,    BATCH, TTL,  IN_DIM, 64,   x30h, x30l, pop,     0);
    CV(0, W_ih0, G4,    TTL,  TTL,    64,   wi0h, wi0l, nullptr, 2048);
    CV(0, W_hh,  G4,    HDIM, HDIM,   HDIM, whhh, whhl, nullptr, 2048);
    CV(0, h0,    BATCH, HDIM, HDIM,   HDIM, h0h,  h0l,  nullptr, 0);
    biasp_kernel<<<(NL * G4 + 255) / 256, 256>>>(b_ih, b_hh, biasp);

    // ---- s1: conversions for layers 1-4, then meta branch + readout weights ----
    CV(s1, W_ihR,                     4 * G4,    HDIM, HDIM, HDIM, wirh, wirl, nullptr, 2048);
    CV(s1, W_hh + (size_t)G4 * HDIM,  4 * G4,    HDIM, HDIM, HDIM,
       whhh + (size_t)G4 * HDIM, whhl + (size_t)G4 * HDIM, nullptr, 2048);
    CV(s1, h0 + (size_t)BATCH * HDIM, 4 * BATCH, HDIM, HDIM, HDIM,
       h0h + (size_t)BATCH * HDIM, h0l + (size_t)BATCH * HDIM, nullptr, 0);
    cudaEventRecord(evC, s1);

    CV(s1, mi + TTL,   BATCH,    30,   IN_DIM, 64,   mih,  mil,  nullptr, 0);
    CV(s1, mW1,        HDIM,     30,   30,     64,   mw1h, mw1l, nullptr, 0);
    CV(s1, mW2,        HDIM,     HDIM, HDIM,   HDIM, mw2h, mw2l, nullptr, 0);
    CV(s1, rW1,        2 * HDIM, HDIM, 2*HDIM, HDIM, r1ah, r1al, nullptr, 0);
    CV(s1, rW1 + HDIM, 2 * HDIM, HDIM, 2*HDIM, HDIM, r1bh, r1bl, nullptr, 0);
    dim3 mGrid(HDIM / 128, BATCH / 128);
    { Seg sg[3] = { {mih, mw1h, 64}, {mil, mw1h, 64}, {mih, mw1l, 64} };
      GL(s1, mGrid, sg, 3, mb1, nullptr, nullptr, nullptr, m1h, m1l, HDIM, 1); }
    { Seg sg[3] = { {m1h, mw2h, HDIM}, {m1l, mw2h, HDIM}, {m1h, mw2l, HDIM} };
      GL(s1, mGrid, sg, 3, mb2, nullptr, nullptr, nullptr, m2h, m2l, HDIM, 1); }
    cudaEventRecord(evJ, s1);

    // ---- default stream: LSTM chain (128x128 CTAs, 2/SM), fused cell, ping-pong ----
    dim3 gGrid(G4 / 128, BATCH / 128);
    for (int l = 0; l < NL; l++) {
        if (l == 1) cudaStreamWaitEvent(0, evC, 0);
        bf16* ah = (l == 0) ? x30h : ((l & 1) ? xAh : xBh);
        bf16* al = (l == 0) ? x30l : ((l & 1) ? xAl : xBl);
        bf16* oh = (l & 1) ? xBh : xAh;
        bf16* ol = (l & 1) ? xBl : xAl;
        int   Kx = l ? HDIM : 64;
        bf16* wh = l ? (wirh + (size_t)(l - 1) * G4 * HDIM) : wi0h;
        bf16* wl = l ? (wirl + (size_t)(l - 1) * G4 * HDIM) : wi0l;
        bf16* hh = h0h + (size_t)l * BATCH * HDIM;
        bf16* hl = h0l + (size_t)l * BATCH * HDIM;
        bf16* Wh = whhh + (size_t)l * G4 * HDIM;
        bf16* Wl = whhl + (size_t)l * G4 * HDIM;
        Seg sg[6] = { {ah, wh, Kx}, {al, wh, Kx}, {ah, wl, Kx},
                      {hh, Wh, HDIM}, {hl, Wh, HDIM}, {hh, Wl, HDIM} };
        GL(0, gGrid, sg, 6, biasp + (size_t)l * G4,
           c0 + (size_t)l * BATCH * HDIM, (l == NL - 1) ? ts : nullptr,
           nullptr, oh, ol, HDIM, 3);
    }
    bf16* xfh = xAh;   // layer 4 (even) wrote buffer A
    bf16* xfl = xAl;

    // join meta branch, then readout
    cudaStreamWaitEvent(0, evJ, 0);
    dim3 zGrid(2 * HDIM / 128, BATCH / 128);
    { Seg sg[6] = { {xfh, r1ah, HDIM}, {xfl, r1ah, HDIM}, {xfh, r1al, HDIM},
                    {m2h, r1bh, HDIM}, {m2l, r1bh, HDIM}, {m2h, r1bl, HDIM} };
      GL(0, zGrid, sg, 6, rb1, nullptr, nullptr, zb, nullptr, nullptr, 2 * HDIM, 2); }

    raw_dnn_kernel<<<BATCH, 256>>>(zb, rW2, rb2, rng, scl, raw, dnn);
    ode_kernel<<<(BATCH + 63) / 64, 64>>>(pop, ccn, mort, dnn, sol);
}

// round 14
// speedup vs baseline: 1.0416x; 1.0416x over previous
#include <cuda_runtime.h>
#include <cuda_bf16.h>
#include <math.h>
#include <stdint.h>

typedef __nv_bfloat16 bf16;

#define BATCH 2048
#define TTL   30
#define IN_DIM 60
#define HDIM  512
#define G4    2048
#define NL    5
#define OUTD  23
#define TPTS  90

// ============================ static scratch ============================
__device__ float g_z    [BATCH * 2 * HDIM];
__device__ float g_biasp[NL * G4];
__device__ bf16  g_x30h[BATCH * 64],  g_x30l[BATCH * 64];
__device__ bf16  g_mih [BATCH * 64],  g_mil [BATCH * 64];
__device__ bf16  g_wi0h[G4 * 64],     g_wi0l[G4 * 64];
__device__ bf16  g_wirh[4 * G4 * HDIM], g_wirl[4 * G4 * HDIM];
__device__ bf16  g_whhh[5 * G4 * HDIM], g_whhl[5 * G4 * HDIM];
__device__ bf16  g_h0h [5 * BATCH * HDIM], g_h0l[5 * BATCH * HDIM];
__device__ bf16  g_mw1h[HDIM * 64],   g_mw1l[HDIM * 64];
__device__ bf16  g_mw2h[HDIM * HDIM], g_mw2l[HDIM * HDIM];
__device__ bf16  g_r1ah[2 * HDIM * HDIM], g_r1al[2 * HDIM * HDIM];
__device__ bf16  g_r1bh[2 * HDIM * HDIM], g_r1bl[2 * HDIM * HDIM];
__device__ bf16  g_xAh [BATCH * HDIM], g_xAl[BATCH * HDIM];
__device__ bf16  g_xBh [BATCH * HDIM], g_xBl[BATCH * HDIM];
__device__ bf16  g_m1h [BATCH * HDIM], g_m1l[BATCH * HDIM];
__device__ bf16  g_m2h [BATCH * HDIM], g_m2l[BATCH * HDIM];

// ============================ helpers ============================
static __device__ __forceinline__ uint32_t smem_u32(const void* p) {
    uint32_t a;
    asm("{ .reg .u64 t; cvta.to.shared.u64 t, %1; cvt.u32.u64 %0, t; }" : "=r"(a) : "l"(p));
    return a;
}
static __device__ __forceinline__ void cpa16(uint32_t d, const void* s) {
    asm volatile("cp.async.cg.shared.global [%0], [%1], 16;" :: "r"(d), "l"(s));
}
static __device__ __forceinline__ void cp_commit() {
    asm volatile("cp.async.commit_group;" ::: "memory");
}
static __device__ __forceinline__ void cp_wait0() {
    asm volatile("cp.async.wait_group 0;" ::: "memory");
}
static __device__ __forceinline__ void cp_wait1() {
    asm volatile("cp.async.wait_group 1;" ::: "memory");
}
static __device__ __forceinline__ void ldsm4(uint32_t* r, uint32_t a) {
    asm volatile("ldmatrix.sync.aligned.m8n8.x4.shared.b16 {%0,%1,%2,%3}, [%4];"
                 : "=r"(r[0]), "=r"(r[1]), "=r"(r[2]), "=r"(r[3]) : "r"(a));
}
static __device__ __forceinline__ void mma16816(float* c, const uint32_t* a, const uint32_t* b) {
    asm volatile("mma.sync.aligned.m16n8k16.row.col.f32.bf16.bf16.f32 "
                 "{%0,%1,%2,%3}, {%4,%5,%6,%7}, {%8,%9}, {%0,%1,%2,%3};"
                 : "+f"(c[0]), "+f"(c[1]), "+f"(c[2]), "+f"(c[3])
                 : "r"(a[0]), "r"(a[1]), "r"(a[2]), "r"(a[3]), "r"(b[0]), "r"(b[1]));
}
static __device__ __forceinline__ float sigf(float x) { return 1.f / (1.f + expf(-x)); }

// ============================ GEMM kernel ============================
// CTA tile 128x128, warps 4(M)x2(N), warp tile 32x64, BK=32, 80B row stride,
// 3-stage cp.async, ONE __syncthreads per chunk.  (Best measured config: R9.)
struct Seg { const bf16* A; const bf16* B; int K; };
struct GArgs {
    Seg s[6]; int nseg;
    const float* bias1;
    const float* c0;      // op==3 (fused lstm cell)
    float* tso;           // op==3 optional float x output
    float* Cf; bf16* Ch; bf16* Cl;
    int ldc; int op;  // 0 none, 1 relu, 2 tanh, 3 lstm-cell (interleaved gates)
};
#define STAGE_B 20480u
#define GEMM_SMEM (20480 * 3)

__global__ __launch_bounds__(256, 2)
void gemm_tc(GArgs args)
{
    extern __shared__ __align__(256) char smem[];
    const uint32_t sb = smem_u32(smem);
    const int tid = threadIdx.x;
    const int wid = tid >> 5;
    const int lane = tid & 31;
    const int bM = blockIdx.y * 128;
    const int bN = blockIdx.x * 128;

    int segBase[7];
    segBase[0] = 0;
#pragma unroll
    for (int i = 0; i < 6; i++)
        segBase[i + 1] = segBase[i] + ((i < args.nseg) ? (args.s[i].K >> 5) : 0);
    const int nch = segBase[6];

    const int wm = (wid >> 1) * 32;
    const int wn = (wid & 1) * 64;

    float ac[2][8][4];
#pragma unroll
    for (int mt = 0; mt < 2; mt++)
#pragma unroll
        for (int nt = 0; nt < 8; nt++)
#pragma unroll
            for (int i = 0; i < 4; i++) ac[mt][nt][i] = 0.f;

    auto slotOf = [&](int cc) -> uint32_t {
        return sb + (uint32_t)(cc % 3) * STAGE_B;
    };
    auto loadChunk = [&](int cc) {
        int s = 0;
#pragma unroll
        for (int i = 0; i < 5; i++) if (cc >= segBase[i + 1]) s = i + 1;
        const bf16* A = args.s[s].A;
        const bf16* B = args.s[s].B;
        const int K = args.s[s].K;
        const int k0 = (cc - segBase[s]) * 32;
        uint32_t st = slotOf(cc);
#pragma unroll
        for (int i = 0; i < 2; i++) {
            int ch = tid + i * 256;
            int row = ch >> 2, cb = ch & 3;
            cpa16(st + (uint32_t)(row * 80 + cb * 16),
                  A + (size_t)(bM + row) * K + k0 + cb * 8);
        }
#pragma unroll
        for (int i = 0; i < 2; i++) {
            int ch = tid + i * 256;
            int row = ch >> 2, cb = ch & 3;
            cpa16(st + 10240u + (uint32_t)(row * 80 + cb * 16),
                  B + (size_t)(bN + row) * K + k0 + cb * 8);
        }
    };

    loadChunk(0); cp_commit();
    if (nch > 1) { loadChunk(1); cp_commit(); }
    for (int cc = 0; cc < nch; cc++) {
        if (cc < nch - 1) cp_wait1(); else cp_wait0();
        __syncthreads();
        if (cc + 2 < nch) { loadChunk(cc + 2); cp_commit(); }
        uint32_t stA = slotOf(cc);
        uint32_t stB = stA + 10240u;
#pragma unroll
        for (int kk = 0; kk < 32; kk += 16) {
            uint32_t af[2][4], bfr[4][4];
#pragma unroll
            for (int mt = 0; mt < 2; mt++)
                ldsm4(af[mt], stA + (uint32_t)((wm + mt * 16 + (lane & 15)) * 80
                                               + (kk + (lane >> 4) * 8) * 2));
#pragma unroll
            for (int p = 0; p < 4; p++)
                ldsm4(bfr[p], stB + (uint32_t)((wn + p * 16 + (lane & 7) + ((lane >> 4) & 1) * 8) * 80
                                               + (kk + ((lane >> 3) & 1) * 8) * 2));
#pragma unroll
            for (int mt = 0; mt < 2; mt++)
#pragma unroll
                for (int nt = 0; nt < 8; nt++)
                    mma16816(ac[mt][nt], af[mt], &bfr[nt >> 1][(nt & 1) * 2]);
        }
    }

    if (args.op == 3) {
        // fused LSTM cell: interleaved gate columns 4h+{i,f,g,o}
#pragma unroll
        for (int mt = 0; mt < 2; mt++)
#pragma unroll
            for (int nt = 0; nt < 8; nt++) {
                int row = bM + wm + mt * 16 + (lane >> 2);
                int col = bN + wn + nt * 8 + 2 * (lane & 3);
                float v0 = ac[mt][nt][0] + args.bias1[col];
                float v1 = ac[mt][nt][1] + args.bias1[col + 1];
                float v2 = ac[mt][nt][2] + args.bias1[col];
                float v3 = ac[mt][nt][3] + args.bias1[col + 1];
                float p0 = __shfl_xor_sync(0xffffffffu, v0, 1);
                float p1 = __shfl_xor_sync(0xffffffffu, v1, 1);
                float p2 = __shfl_xor_sync(0xffffffffu, v2, 1);
                float p3 = __shfl_xor_sync(0xffffffffu, v3, 1);
                if (!(lane & 1)) {
                    int h = col >> 2;
                    float c1 = args.c0[(size_t)row * HDIM + h];
                    float c2 = args.c0[(size_t)(row + 8) * HDIM + h];
                    float cc1 = sigf(v1) * c1 + sigf(v0) * tanhf(p0);
                    float x1 = sigf(p1) * tanhf(cc1);
                    float cc2 = sigf(v3) * c2 + sigf(v2) * tanhf(p2);
                    float x2 = sigf(p3) * tanhf(cc2);
                    bf16 h1 = __float2bfloat16(x1);
                    bf16 h2 = __float2bfloat16(x2);
                    size_t i1 = (size_t)row * HDIM + h;
                    size_t i2 = (size_t)(row + 8) * HDIM + h;
                    args.Ch[i1] = h1;
                    args.Cl[i1] = __float2bfloat16(x1 - __bfloat162float(h1));
                    args.Ch[i2] = h2;
                    args.Cl[i2] = __float2bfloat16(x2 - __bfloat162float(h2));
                    if (args.tso) { args.tso[i1] = x1; args.tso[i2] = x2; }
                }
            }
        return;
    }

    auto storePair = [&](int row, int col, float v0, float v1) {
        if (args.bias1) { v0 += args.bias1[col]; v1 += args.bias1[col + 1]; }
        if (args.op == 1)      { v0 = fmaxf(v0, 0.f); v1 = fmaxf(v1, 0.f); }
        else if (args.op == 2) { v0 = tanhf(v0); v1 = tanhf(v1); }
        size_t base = (size_t)row * args.ldc + col;
        if (args.Cf)
            *reinterpret_cast<float2*>(args.Cf + base) = make_float2(v0, v1);
        if (args.Ch) {
            bf16 h0 = __float2bfloat16(v0), h1 = __float2bfloat16(v1);
            bf16 l0 = __float2bfloat16(v0 - __bfloat162float(h0));
            bf16 l1 = __float2bfloat16(v1 - __bfloat162float(h1));
            *reinterpret_cast<uint32_t*>(args.Ch + base) =
                (uint32_t)__bfloat16_as_ushort(h0) | ((uint32_t)__bfloat16_as_ushort(h1) << 16);
            *reinterpret_cast<uint32_t*>(args.Cl + base) =
                (uint32_t)__bfloat16_as_ushort(l0) | ((uint32_t)__bfloat16_as_ushort(l1) << 16);
        }
    };
#pragma unroll
    for (int mt = 0; mt < 2; mt++)
#pragma unroll
        for (int nt = 0; nt < 8; nt++) {
            int row = bM + wm + mt * 16 + (lane >> 2);
            int col = bN + wn + nt * 8 + 2 * (lane & 3);
            storePair(row,     col, ac[mt][nt][0], ac[mt][nt][1]);
            storePair(row + 8, col, ac[mt][nt][2], ac[mt][nt][3]);
        }
}

// ============================ conversion ============================
__global__ void conv_hl(const float* __restrict__ src, int rows, int Ks, int ld, int Kd,
                        bf16* __restrict__ h, bf16* __restrict__ l,
                        const float* __restrict__ divr, int permBlock)
{
    int idx = blockIdx.x * blockDim.x + threadIdx.x;
    if (idx >= rows * Kd) return;
    int r = idx / Kd, k = idx - r * Kd;
    int sr = r;
    if (permBlock) {
        int blk = r / permBlock, rr = r - blk * permBlock;
        sr = blk * permBlock + (rr & 3) * 512 + (rr >> 2);
    }
    float v = (k < Ks) ? src[(size_t)sr * ld + k] : 0.f;
    if (divr) v /= divr[r];
    bf16 hb = __float2bfloat16(v);
    h[idx] = hb;
    l[idx] = __float2bfloat16(v - __bfloat162float(hb));
}

__global__ void biasp_kernel(const float* __restrict__ b_ih, const float* __restrict__ b_hh,
                             float* __restrict__ bp)
{
    int idx = blockIdx.x * blockDim.x + threadIdx.x;
    if (idx >= NL * G4) return;
    int l = idx >> 11, rr = idx & 2047;
    int sr = (rr & 3) * 512 + (rr >> 2);
    bp[idx] = b_ih[l * G4 + sr] + b_hh[l * G4 + sr];
}

__global__ void raw_dnn_kernel(const float* __restrict__ z, const float* __restrict__ W2,
                               const float* __restrict__ b2, const float* __restrict__ rng,
                               const void* __restrict__ scale_ptr,
                               float* __restrict__ raw_out, float* __restrict__ dnn_out)
{
    __shared__ float zs[2 * HDIM];
    int b = blockIdx.x;
    const float* zr = z + (size_t)b * 2 * HDIM;
    for (int i = threadIdx.x; i < 2 * HDIM; i += blockDim.x) zs[i] = zr[i];
    __syncthreads();
    int warp = threadIdx.x >> 5, lane = threadIdx.x & 31;
    int bits = *(const int*)scale_ptr;
    float f = __int_as_float(bits);
    float af = fabsf(f);
    float s = (af >= 1e-30f && af <= 1e30f) ? f : (float)bits;
    for (int o = warp; o < OUTD; o += 8) {
        const float* w = W2 + (size_t)o * 2 * HDIM;
        float acc = 0.f;
        for (int k = lane; k < 2 * HDIM; k += 32) acc += zs[k] * w[k];
#pragma unroll
        for (int off = 16; off; off >>= 1) acc += __shfl_xor_sync(0xffffffffu, acc, off);
        if (lane == 0) {
            float r = acc + b2[o];
            raw_out[(size_t)b * OUTD + o] = r;
            dnn_out[(size_t)b * OUTD + o] = (1.f / (1.f + expf(-r * s))) * rng[o];
        }
    }
}

// ============================ ODE ============================
#define LN2D 0.6931471805599453
#define C_RI  ((float)(LN2D / 5.0))
#define C_RD  ((float)(LN2D / 2.0))
#define C_RRI ((float)(LN2D / 10.0))
#define C_RRH ((float)(LN2D / 15.0))
#define C_RRV ((float)(LN2D / 10.0))
#define TWO_OVER_PI 0.6366197723675814f
#define HALF_PI     1.5707963267948966f

__device__ __forceinline__ void covid_deriv(const float y[16], float gam, float pdt,
                                            float aN, float r_dth, float d[16])
{
    float S = y[0], E = y[1], I = y[2];
    float AR = y[3], DHR = y[4], DQR = y[5], AD = y[6], DHD = y[7], DQD = y[8];
    float DVR = y[12], DVD = y[13];
    float inf = aN * gam * S * I;
    float det = C_RD * I;
    float d1m = det * (1.f - pdt);
    float dp  = det * pdt;
    d[0] = -inf;
    d[1] = inf - C_RI * E;
    d[2] = C_RI * E - det;
    d[3] = d1m * 0.8f - C_RRI * AR;
    d[4] = d1m * 0.03f - C_RRH * DHR;
    d[5] = d1m * 0.17f - C_RRI * DQR;
    d[6] = dp * 0.8f - r_dth * AD;
    d[7] = dp * 0.03f - r_dth * DHD;
    d[8] = dp * 0.17f - r_dth * DQD;
    d[9] = C_RRI * (AR + DQR) + C_RRH * DHR;
    d[10] = r_dth * (AD + DQD + DHD);
    d[11] = det * 0.03f;
    d[12] = d1m * 0.0075f - C_RRV * DVR;
    d[13] = dp * 0.0075f - r_dth * DVD;
    d[14] = r_dth * (DHD + DQD);
    d[15] = det * 0.2f;
}
__device__ __forceinline__ float gam_f(float t, float days, float rs20,
                                       float jump, float t_jump, float inv2s2)
{
    float dtj = t - t_jump;
    return TWO_OVER_PI * atanf((days - t) * rs20) + 1.0f + jump * __expf(-dtj * dtj * inv2s2);
}
__device__ __forceinline__ float pdt_f(float t, float pc, float rdd20)
{
    return pc * (atanf(-t * rdd20) + HALF_PI) + 0.001f;
}

__global__ void ode_kernel(const float* __restrict__ pop, const float* __restrict__ ccn,
                           const float* __restrict__ mort, const float* __restrict__ dnn,
                           float* __restrict__ sol)
{
    int b = blockIdx.x * blockDim.x + threadIdx.x;
    if (b >= BATCH) return;
    const float* dn = dnn + (size_t)b * OUTD;
    float alpha = dn[11], days = dn[12], r_s = dn[13], r_dth = dn[14], p_dth = dn[15];
    float r_dthdecay = dn[16], k1 = dn[17], k2 = dn[18], jump = dn[19];
    float t_jump = dn[20], stdn = dn[21];

    float N = pop[b];
    float PopI = ccn[b];
    float PopD = floorf(mort[b] * PopI);
    float R0 = (PopI - PopD > 5.0f * PopD) ? 5.0f * PopD : 0.0f;
    float PopCI = PopI - PopD - R0;
    float ciPD = PopCI / 0.2f;
    float omp = 1.0f - p_dth;

    float y[16];
    y[0] = N - ciPD * (k1 + k2) - R0 / 0.2f - PopD / 0.2f;
    y[1] = ciPD * k1;  y[2] = ciPD * k2;
    y[3] = (ciPD - PopCI) * omp;
    y[4] = PopCI * 0.15f * omp;
    y[5] = PopCI * 0.85f * omp;
    y[6] = (ciPD - PopCI) * p_dth;
    y[7] = PopCI * 0.15f * p_dth;
    y[8] = PopCI * 0.85f * p_dth;
    y[9] = R0 / 0.2f;  y[10] = PopD / 0.2f;
    y[11] = PopCI * 0.15f;
    y[12] = PopCI * 0.0375f * omp;
    y[13] = PopCI * 0.0375f * p_dth;
    y[14] = PopD;  y[15] = PopI;

    float* srow = sol + (size_t)b * TPTS * 16;
#pragma unroll
    for (int i = 0; i < 16; i++) srow[i] = y[i];

    float aN = alpha / N;
    float rs20 = r_s * 0.05f;
    float rdd20 = r_dthdecay * 0.05f;
    float inv2s2 = 1.0f / (2.0f * stdn * stdn);
    float pc = TWO_OVER_PI * (p_dth - 0.001f);

    for (int seg = 0; seg < TPTS - 1; seg++) {
        float t0 = (float)seg;
        for (int j = 0; j < 10; j++) {
            float t = t0 + (float)j * 0.1f;
            float g1 = gam_f(t, days, rs20, jump, t_jump, inv2s2);
            float g2 = gam_f(t + 0.05f, days, rs20, jump, t_jump, inv2s2);
            float g3 = gam_f(t + 0.1f, days, rs20, jump, t_jump, inv2s2);
            float p1 = pdt_f(t, pc, rdd20);
            float p2 = pdt_f(t + 0.05f, pc, rdd20);
            float p3 = pdt_f(t + 0.1f, pc, rdd20);
            float k[16], acc[16], yy[16];
            covid_deriv(y, g1, p1, aN, r_dth, k);
#pragma unroll
            for (int i = 0; i < 16; i++) { acc[i] = k[i]; yy[i] = y[i] + 0.05f * k[i]; }
            covid_deriv(yy, g2, p2, aN, r_dth, k);
#pragma unroll
            for (int i = 0; i < 16; i++) { acc[i] += 2.f * k[i]; yy[i] = y[i] + 0.05f * k[i]; }
            covid_deriv(yy, g2, p2, aN, r_dth, k);
#pragma unroll
            for (int i = 0; i < 16; i++) { acc[i] += 2.f * k[i]; yy[i] = y[i] + 0.1f * k[i]; }
            covid_deriv(yy, g3, p3, aN, r_dth, k);
#pragma unroll
            for (int i = 0; i < 16; i++) y[i] += (0.1f / 6.0f) * (acc[i] + k[i]);
        }
        float* o = srow + (size_t)(seg + 1) * 16;
#pragma unroll
        for (int i = 0; i < 16; i++) o[i] = y[i];
    }
}

// ============================ launch ============================
static void* sym(const void* s) { void* p; cudaGetSymbolAddress(&p, s); return p; }

extern "C" void kernel_launch(void* const* d_in, const int* in_sizes, int n_in,
                              void* d_out, int out_size)
{
    const float* mi    = (const float*)d_in[0];
    const float* pop   = (const float*)d_in[1];
    const float* ccn   = (const float*)d_in[2];
    const float* mort  = (const float*)d_in[3];
    const float* h0    = (const float*)d_in[4];
    const float* c0    = (const float*)d_in[5];
    const float* W_ih0 = (const float*)d_in[6];
    const float* W_ihR = (const float*)d_in[7];
    const float* W_hh  = (const float*)d_in[8];
    const float* b_ih  = (const float*)d_in[9];
    const float* b_hh  = (const float*)d_in[10];
    const float* mW1   = (const float*)d_in[11];
    const float* mb1   = (const float*)d_in[12];
    const float* mW2   = (const float*)d_in[13];
    const float* mb2   = (const float*)d_in[14];
    const float* rW1   = (const float*)d_in[15];
    const float* rb1   = (const float*)d_in[16];
    const float* rW2   = (const float*)d_in[17];
    const float* rb2   = (const float*)d_in[18];
    const float* rng   = (const float*)d_in[19];
    const void*  scl   = d_in[20];

    float* out = (float*)d_out;
    float* sol = out;
    float* dnn = out + (size_t)BATCH * TPTS * 16;
    float* ts  = dnn + (size_t)BATCH * OUTD;
    float* raw = ts  + (size_t)BATCH * HDIM;

    float* zb    = (float*)sym(g_z);
    float* biasp = (float*)sym(g_biasp);
    bf16 *x30h = (bf16*)sym(g_x30h), *x30l = (bf16*)sym(g_x30l);
    bf16 *mih  = (bf16*)sym(g_mih),  *mil  = (bf16*)sym(g_mil);
    bf16 *wi0h = (bf16*)sym(g_wi0h), *wi0l = (bf16*)sym(g_wi0l);
    bf16 *wirh = (bf16*)sym(g_wirh), *wirl = (bf16*)sym(g_wirl);
    bf16 *whhh = (bf16*)sym(g_whhh), *whhl = (bf16*)sym(g_whhl);
    bf16 *h0h  = (bf16*)sym(g_h0h),  *h0l  = (bf16*)sym(g_h0l);
    bf16 *mw1h = (bf16*)sym(g_mw1h), *mw1l = (bf16*)sym(g_mw1l);
    bf16 *mw2h = (bf16*)sym(g_mw2h), *mw2l = (bf16*)sym(g_mw2l);
    bf16 *r1ah = (bf16*)sym(g_r1ah), *r1al = (bf16*)sym(g_r1al);
    bf16 *r1bh = (bf16*)sym(g_r1bh), *r1bl = (bf16*)sym(g_r1bl);
    bf16 *xAh  = (bf16*)sym(g_xAh),  *xAl  = (bf16*)sym(g_xAl);
    bf16 *xBh  = (bf16*)sym(g_xBh),  *xBl  = (bf16*)sym(g_xBl);
    bf16 *m1h  = (bf16*)sym(g_m1h),  *m1l  = (bf16*)sym(g_m1l);
    bf16 *m2h  = (bf16*)sym(g_m2h),  *m2l  = (bf16*)sym(g_m2l);

    static cudaStream_t s1 = nullptr;
    static cudaEvent_t  evF = nullptr, evJ = nullptr, evC = nullptr;
    if (!s1) {
        cudaStreamCreateWithFlags(&s1, cudaStreamNonBlocking);
        cudaEventCreateWithFlags(&evF, cudaEventDisableTiming);
        cudaEventCreateWithFlags(&evJ, cudaEventDisableTiming);
        cudaEventCreateWithFlags(&evC, cudaEventDisableTiming);
        cudaFuncSetAttribute(gemm_tc, cudaFuncAttributeMaxDynamicSharedMemorySize, GEMM_SMEM);
    }

    auto CV = [&](cudaStream_t st, const float* s, int rows, int Ks, int ld, int Kd,
                  bf16* h, bf16* l, const float* dv, int perm) {
        int n = rows * Kd;
        conv_hl<<<(n + 255) / 256, 256, 0, st>>>(s, rows, Ks, ld, Kd, h, l, dv, perm);
    };
    auto GL = [&](cudaStream_t st, dim3 grid, Seg* sg, int ns, const float* b1,
                  const float* c0p, float* tso,
                  float* Cf, bf16* Ch, bf16* Cl, int ldc, int op) {
        GArgs a = {};
        for (int i = 0; i < ns; i++) a.s[i] = sg[i];
        a.nseg = ns; a.bias1 = b1; a.c0 = c0p; a.tso = tso;
        a.Cf = Cf; a.Ch = Ch; a.Cl = Cl; a.ldc = ldc; a.op = op;
        gemm_tc<<<grid, 256, GEMM_SMEM, st>>>(a);
    };

    // fork s1 from capture origin
    cudaEventRecord(evF, 0);
    cudaStreamWaitEvent(s1, evF, 0);

    // ---- default stream: ONLY layer-0-critical conversions ----
    CV(0, mi,    BATCH, TTL,  IN_DIM, 64,   x30h, x30l, pop,     0);
    CV(0, W_ih0, G4,    TTL,  TTL,    64,   wi0h, wi0l, nullptr, 2048);
    CV(0, W_hh,  G4,    HDIM, HDIM,   HDIM, whhh, whhl, nullptr, 2048);
    CV(0, h0,    BATCH, HDIM, HDIM,   HDIM, h0h,  h0l,  nullptr, 0);
    biasp_kernel<<<(NL * G4 + 255) / 256, 256>>>(b_ih, b_hh, biasp);

    // ---- s1: conversions for layers 1-4, then meta branch + readout weights ----
    CV(s1, W_ihR,                     4 * G4,    HDIM, HDIM, HDIM, wirh, wirl, nullptr, 2048);
    CV(s1, W_hh + (size_t)G4 * HDIM,  4 * G4,    HDIM, HDIM, HDIM,
       whhh + (size_t)G4 * HDIM, whhl + (size_t)G4 * HDIM, nullptr, 2048);
    CV(s1, h0 + (size_t)BATCH * HDIM, 4 * BATCH, HDIM, HDIM, HDIM,
       h0h + (size_t)BATCH * HDIM, h0l + (size_t)BATCH * HDIM, nullptr, 0);
    cudaEventRecord(evC, s1);

    CV(s1, mi + TTL,   BATCH,    30,   IN_DIM, 64,   mih,  mil,  nullptr, 0);
    CV(s1, mW1,        HDIM,     30,   30,     64,   mw1h, mw1l, nullptr, 0);
    CV(s1, mW2,        HDIM,     HDIM, HDIM,   HDIM, mw2h, mw2l, nullptr, 0);
    CV(s1, rW1,        2 * HDIM, HDIM, 2*HDIM, HDIM, r1ah, r1al, nullptr, 0);
    CV(s1, rW1 + HDIM, 2 * HDIM, HDIM, 2*HDIM, HDIM, r1bh, r1bl, nullptr, 0);
    dim3 mGrid(HDIM / 128, BATCH / 128);
    { Seg sg[3] = { {mih, mw1h, 64}, {mil, mw1h, 64}, {mih, mw1l, 64} };
      GL(s1, mGrid, sg, 3, mb1, nullptr, nullptr, nullptr, m1h, m1l, HDIM, 1); }
    { Seg sg[3] = { {m1h, mw2h, HDIM}, {m1l, mw2h, HDIM}, {m1h, mw2l, HDIM} };
      GL(s1, mGrid, sg, 3, mb2, nullptr, nullptr, nullptr, m2h, m2l, HDIM, 1); }
    cudaEventRecord(evJ, s1);

    // ---- default stream: LSTM chain (128x128 CTAs, 2/SM), fused cell, ping-pong ----
    dim3 gGrid(G4 / 128, BATCH / 128);
    for (int l = 0; l < NL; l++) {
        if (l == 1) cudaStreamWaitEvent(0, evC, 0);
        bf16* ah = (l == 0) ? x30h : ((l & 1) ? xAh : xBh);
        bf16* al = (l == 0) ? x30l : ((l & 1) ? xAl : xBl);
        bf16* oh = (l & 1) ? xBh : xAh;
        bf16* ol = (l & 1) ? xBl : xAl;
        int   Kx = l ? HDIM : 64;
        bf16* wh = l ? (wirh + (size_t)(l - 1) * G4 * HDIM) : wi0h;
        bf16* wl = l ? (wirl + (size_t)(l - 1) * G4 * HDIM) : wi0l;
        bf16* hh = h0h + (size_t)l * BATCH * HDIM;
        bf16* hl = h0l + (size_t)l * BATCH * HDIM;
        bf16* Wh = whhh + (size_t)l * G4 * HDIM;
        bf16* Wl = whhl + (size_t)l * G4 * HDIM;
        Seg sg[6] = { {ah, wh, Kx}, {al, wh, Kx}, {ah, wl, Kx},
                      {hh, Wh, HDIM}, {hl, Wh, HDIM}, {hh, Wl, HDIM} };
        GL(0, gGrid, sg, 6, biasp + (size_t)l * G4,
           c0 + (size_t)l * BATCH * HDIM, (l == NL - 1) ? ts : nullptr,
           nullptr, oh, ol, HDIM, 3);
    }
    bf16* xfh = xAh;   // layer 4 (even) wrote buffer A
    bf16* xfl = xAl;

    // join meta branch, then readout
    cudaStreamWaitEvent(0, evJ, 0);
    dim3 zGrid(2 * HDIM / 128, BATCH / 128);
    { Seg sg[6] = { {xfh, r1ah, HDIM}, {xfl, r1ah, HDIM}, {xfh, r1al, HDIM},
                    {m2h, r1bh, HDIM}, {m2l, r1bh, HDIM}, {m2h, r1bl, HDIM} };
      GL(0, zGrid, sg, 6, rb1, nullptr, nullptr, zb, nullptr, nullptr, 2 * HDIM, 2); }

    raw_dnn_kernel<<<BATCH, 256>>>(zb, rW2, rb2, rng, scl, raw, dnn);
    ode_kernel<<<(BATCH + 63) / 64, 64>>>(pop, ccn, mort, dnn, sol);
}

// round 15
// speedup vs baseline: 1.1511x; 1.1051x over previous
#include <cuda_runtime.h>
#include <cuda_bf16.h>
#include <math.h>
#include <stdint.h>

typedef __nv_bfloat16 bf16;

#define BATCH 2048
#define TTL   30
#define IN_DIM 60
#define HDIM  512
#define G4    2048
#define NL    5
#define OUTD  23
#define TPTS  90

// ============================ static scratch ============================
__device__ float g_z    [BATCH * 2 * HDIM];
__device__ float g_biasp[NL * G4];
__device__ bf16  g_x30h[BATCH * 64],  g_x30l[BATCH * 64];
__device__ bf16  g_mih [BATCH * 64],  g_mil [BATCH * 64];
__device__ bf16  g_wi0h[G4 * 64],     g_wi0l[G4 * 64];
__device__ bf16  g_wirh[4 * G4 * HDIM], g_wirl[4 * G4 * HDIM];
__device__ bf16  g_whhh[5 * G4 * HDIM], g_whhl[5 * G4 * HDIM];
__device__ bf16  g_h0h [5 * BATCH * HDIM], g_h0l[5 * BATCH * HDIM];
__device__ bf16  g_mw1h[HDIM * 64],   g_mw1l[HDIM * 64];
__device__ bf16  g_mw2h[HDIM * HDIM], g_mw2l[HDIM * HDIM];
__device__ bf16  g_r1ah[2 * HDIM * HDIM], g_r1al[2 * HDIM * HDIM];
__device__ bf16  g_r1bh[2 * HDIM * HDIM], g_r1bl[2 * HDIM * HDIM];
__device__ bf16  g_xAh [BATCH * HDIM], g_xAl[BATCH * HDIM];
__device__ bf16  g_xBh [BATCH * HDIM], g_xBl[BATCH * HDIM];
__device__ bf16  g_m1h [BATCH * HDIM], g_m1l[BATCH * HDIM];
__device__ bf16  g_m2h [BATCH * HDIM], g_m2l[BATCH * HDIM];

// ============================ helpers ============================
static __device__ __forceinline__ uint32_t smem_u32(const void* p) {
    uint32_t a;
    asm("{ .reg .u64 t; cvta.to.shared.u64 t, %1; cvt.u32.u64 %0, t; }" : "=r"(a) : "l"(p));
    return a;
}
static __device__ __forceinline__ void cpa16(uint32_t d, const void* s) {
    asm volatile("cp.async.cg.shared.global [%0], [%1], 16;" :: "r"(d), "l"(s));
}
static __device__ __forceinline__ void cp_commit() {
    asm volatile("cp.async.commit_group;" ::: "memory");
}
static __device__ __forceinline__ void cp_wait0() {
    asm volatile("cp.async.wait_group 0;" ::: "memory");
}
static __device__ __forceinline__ void cp_wait1() {
    asm volatile("cp.async.wait_group 1;" ::: "memory");
}
static __device__ __forceinline__ void ldsm4(uint32_t* r, uint32_t a) {
    asm volatile("ldmatrix.sync.aligned.m8n8.x4.shared.b16 {%0,%1,%2,%3}, [%4];"
                 : "=r"(r[0]), "=r"(r[1]), "=r"(r[2]), "=r"(r[3]) : "r"(a));
}
static __device__ __forceinline__ void mma16816(float* c, const uint32_t* a, const uint32_t* b) {
    asm volatile("mma.sync.aligned.m16n8k16.row.col.f32.bf16.bf16.f32 "
                 "{%0,%1,%2,%3}, {%4,%5,%6,%7}, {%8,%9}, {%0,%1,%2,%3};"
                 : "+f"(c[0]), "+f"(c[1]), "+f"(c[2]), "+f"(c[3])
                 : "r"(a[0]), "r"(a[1]), "r"(a[2]), "r"(a[3]), "r"(b[0]), "r"(b[1]));
}
static __device__ __forceinline__ float sigf(float x) { return 1.f / (1.f + expf(-x)); }

// ============================ GEMM kernel ============================
// CTA tile 128x128, warps 4(M)x2(N), warp tile 32x64, BK=32, 80B row stride,
// 3-stage cp.async, ONE __syncthreads per chunk.
struct Seg { const bf16* A; const bf16* B; int K; };
struct GArgs {
    Seg s[6]; int nseg;
    const float* bias1;
    const float* addC;    // optional fp32 pre-add (K-split accumulate)
    const float* c0;      // op==3 (fused lstm cell)
    float* tso;           // op==3 optional float x output
    float* Cf; bf16* Ch; bf16* Cl;
    int ldc; int op;  // 0 none, 1 relu, 2 tanh, 3 lstm-cell (interleaved gates)
};
#define STAGE_B 20480u
#define GEMM_SMEM (20480 * 3)

__global__ __launch_bounds__(256, 2)
void gemm_tc(GArgs args)
{
    extern __shared__ __align__(256) char smem[];
    const uint32_t sb = smem_u32(smem);
    const int tid = threadIdx.x;
    const int wid = tid >> 5;
    const int lane = tid & 31;
    const int bM = blockIdx.y * 128;
    const int bN = blockIdx.x * 128;

    int segBase[7];
    segBase[0] = 0;
#pragma unroll
    for (int i = 0; i < 6; i++)
        segBase[i + 1] = segBase[i] + ((i < args.nseg) ? (args.s[i].K >> 5) : 0);
    const int nch = segBase[6];

    const int wm = (wid >> 1) * 32;
    const int wn = (wid & 1) * 64;

    float ac[2][8][4];
#pragma unroll
    for (int mt = 0; mt < 2; mt++)
#pragma unroll
        for (int nt = 0; nt < 8; nt++)
#pragma unroll
            for (int i = 0; i < 4; i++) ac[mt][nt][i] = 0.f;

    auto slotOf = [&](int cc) -> uint32_t {
        return sb + (uint32_t)(cc % 3) * STAGE_B;
    };
    auto loadChunk = [&](int cc) {
        int s = 0;
#pragma unroll
        for (int i = 0; i < 5; i++) if (cc >= segBase[i + 1]) s = i + 1;
        const bf16* A = args.s[s].A;
        const bf16* B = args.s[s].B;
        const int K = args.s[s].K;
        const int k0 = (cc - segBase[s]) * 32;
        uint32_t st = slotOf(cc);
#pragma unroll
        for (int i = 0; i < 2; i++) {
            int ch = tid + i * 256;
            int row = ch >> 2, cb = ch & 3;
            cpa16(st + (uint32_t)(row * 80 + cb * 16),
                  A + (size_t)(bM + row) * K + k0 + cb * 8);
        }
#pragma unroll
        for (int i = 0; i < 2; i++) {
            int ch = tid + i * 256;
            int row = ch >> 2, cb = ch & 3;
            cpa16(st + 10240u + (uint32_t)(row * 80 + cb * 16),
                  B + (size_t)(bN + row) * K + k0 + cb * 8);
        }
    };

    loadChunk(0); cp_commit();
    if (nch > 1) { loadChunk(1); cp_commit(); }
    for (int cc = 0; cc < nch; cc++) {
        if (cc < nch - 1) cp_wait1(); else cp_wait0();
        __syncthreads();
        if (cc + 2 < nch) { loadChunk(cc + 2); cp_commit(); }
        uint32_t stA = slotOf(cc);
        uint32_t stB = stA + 10240u;
#pragma unroll
        for (int kk = 0; kk < 32; kk += 16) {
            uint32_t af[2][4], bfr[4][4];
#pragma unroll
            for (int mt = 0; mt < 2; mt++)
                ldsm4(af[mt], stA + (uint32_t)((wm + mt * 16 + (lane & 15)) * 80
                                               + (kk + (lane >> 4) * 8) * 2));
#pragma unroll
            for (int p = 0; p < 4; p++)
                ldsm4(bfr[p], stB + (uint32_t)((wn + p * 16 + (lane & 7) + ((lane >> 4) & 1) * 8) * 80
                                               + (kk + ((lane >> 3) & 1) * 8) * 2));
#pragma unroll
            for (int mt = 0; mt < 2; mt++)
#pragma unroll
                for (int nt = 0; nt < 8; nt++)
                    mma16816(ac[mt][nt], af[mt], &bfr[nt >> 1][(nt & 1) * 2]);
        }
    }

    if (args.op == 3) {
        // fused LSTM cell: interleaved gate columns 4h+{i,f,g,o}
#pragma unroll
        for (int mt = 0; mt < 2; mt++)
#pragma unroll
            for (int nt = 0; nt < 8; nt++) {
                int row = bM + wm + mt * 16 + (lane >> 2);
                int col = bN + wn + nt * 8 + 2 * (lane & 3);
                float v0 = ac[mt][nt][0] + args.bias1[col];
                float v1 = ac[mt][nt][1] + args.bias1[col + 1];
                float v2 = ac[mt][nt][2] + args.bias1[col];
                float v3 = ac[mt][nt][3] + args.bias1[col + 1];
                float p0 = __shfl_xor_sync(0xffffffffu, v0, 1);
                float p1 = __shfl_xor_sync(0xffffffffu, v1, 1);
                float p2 = __shfl_xor_sync(0xffffffffu, v2, 1);
                float p3 = __shfl_xor_sync(0xffffffffu, v3, 1);
                if (!(lane & 1)) {
                    int h = col >> 2;
                    float c1 = args.c0[(size_t)row * HDIM + h];
                    float c2 = args.c0[(size_t)(row + 8) * HDIM + h];
                    float cc1 = sigf(v1) * c1 + sigf(v0) * tanhf(p0);
                    float x1 = sigf(p1) * tanhf(cc1);
                    float cc2 = sigf(v3) * c2 + sigf(v2) * tanhf(p2);
                    float x2 = sigf(p3) * tanhf(cc2);
                    bf16 h1 = __float2bfloat16(x1);
                    bf16 h2 = __float2bfloat16(x2);
                    size_t i1 = (size_t)row * HDIM + h;
                    size_t i2 = (size_t)(row + 8) * HDIM + h;
                    args.Ch[i1] = h1;
                    args.Cl[i1] = __float2bfloat16(x1 - __bfloat162float(h1));
                    args.Ch[i2] = h2;
                    args.Cl[i2] = __float2bfloat16(x2 - __bfloat162float(h2));
                    if (args.tso) { args.tso[i1] = x1; args.tso[i2] = x2; }
                }
            }
        return;
    }

    auto storePair = [&](int row, int col, float v0, float v1) {
        size_t base = (size_t)row * args.ldc + col;
        if (args.bias1) { v0 += args.bias1[col]; v1 += args.bias1[col + 1]; }
        if (args.addC)  { v0 += args.addC[base]; v1 += args.addC[base + 1]; }
        if (args.op == 1)      { v0 = fmaxf(v0, 0.f); v1 = fmaxf(v1, 0.f); }
        else if (args.op == 2) { v0 = tanhf(v0); v1 = tanhf(v1); }
        if (args.Cf)
            *reinterpret_cast<float2*>(args.Cf + base) = make_float2(v0, v1);
        if (args.Ch) {
            bf16 h0 = __float2bfloat16(v0), h1 = __float2bfloat16(v1);
            bf16 l0 = __float2bfloat16(v0 - __bfloat162float(h0));
            bf16 l1 = __float2bfloat16(v1 - __bfloat162float(h1));
            *reinterpret_cast<uint32_t*>(args.Ch + base) =
                (uint32_t)__bfloat16_as_ushort(h0) | ((uint32_t)__bfloat16_as_ushort(h1) << 16);
            *reinterpret_cast<uint32_t*>(args.Cl + base) =
                (uint32_t)__bfloat16_as_ushort(l0) | ((uint32_t)__bfloat16_as_ushort(l1) << 16);
        }
    };
#pragma unroll
    for (int mt = 0; mt < 2; mt++)
#pragma unroll
        for (int nt = 0; nt < 8; nt++) {
            int row = bM + wm + mt * 16 + (lane >> 2);
            int col = bN + wn + nt * 8 + 2 * (lane & 3);
            storePair(row,     col, ac[mt][nt][0], ac[mt][nt][1]);
            storePair(row + 8, col, ac[mt][nt][2], ac[mt][nt][3]);
        }
}

// ============================ conversion ============================
__global__ void conv_hl(const float* __restrict__ src, int rows, int Ks, int ld, int Kd,
                        bf16* __restrict__ h, bf16* __restrict__ l,
                        const float* __restrict__ divr, int permBlock)
{
    int idx = blockIdx.x * blockDim.x + threadIdx.x;
    if (idx >= rows * Kd) return;
    int r = idx / Kd, k = idx - r * Kd;
    int sr = r;
    if (permBlock) {
        int blk = r / permBlock, rr = r - blk * permBlock;
        sr = blk * permBlock + (rr & 3) * 512 + (rr >> 2);
    }
    float v = (k < Ks) ? src[(size_t)sr * ld + k] : 0.f;
    if (divr) v /= divr[r];
    bf16 hb = __float2bfloat16(v);
    h[idx] = hb;
    l[idx] = __float2bfloat16(v - __bfloat162float(hb));
}

__global__ void biasp_kernel(const float* __restrict__ b_ih, const float* __restrict__ b_hh,
                             float* __restrict__ bp)
{
    int idx = blockIdx.x * blockDim.x + threadIdx.x;
    if (idx >= NL * G4) return;
    int l = idx >> 11, rr = idx & 2047;
    int sr = (rr & 3) * 512 + (rr >> 2);
    bp[idx] = b_ih[l * G4 + sr] + b_hh[l * G4 + sr];
}

__global__ void raw_dnn_kernel(const float* __restrict__ z, const float* __restrict__ W2,
                               const float* __restrict__ b2, const float* __restrict__ rng,
                               const void* __restrict__ scale_ptr,
                               float* __restrict__ raw_out, float* __restrict__ dnn_out)
{
    __shared__ float zs[2 * HDIM];
    int b = blockIdx.x;
    const float* zr = z + (size_t)b * 2 * HDIM;
    for (int i = threadIdx.x; i < 2 * HDIM; i += blockDim.x) zs[i] = zr[i];
    __syncthreads();
    int warp = threadIdx.x >> 5, lane = threadIdx.x & 31;
    int bits = *(const int*)scale_ptr;
    float f = __int_as_float(bits);
    float af = fabsf(f);
    float s = (af >= 1e-30f && af <= 1e30f) ? f : (float)bits;
    for (int o = warp; o < OUTD; o += 8) {
        const float* w = W2 + (size_t)o * 2 * HDIM;
        float acc = 0.f;
        for (int k = lane; k < 2 * HDIM; k += 32) acc += zs[k] * w[k];
#pragma unroll
        for (int off = 16; off; off >>= 1) acc += __shfl_xor_sync(0xffffffffu, acc, off);
        if (lane == 0) {
            float r = acc + b2[o];
            raw_out[(size_t)b * OUTD + o] = r;
            dnn_out[(size_t)b * OUTD + o] = (1.f / (1.f + expf(-r * s))) * rng[o];
        }
    }
}

// ============================ ODE ============================
#define LN2D 0.6931471805599453
#define C_RI  ((float)(LN2D / 5.0))
#define C_RD  ((float)(LN2D / 2.0))
#define C_RRI ((float)(LN2D / 10.0))
#define C_RRH ((float)(LN2D / 15.0))
#define C_RRV ((float)(LN2D / 10.0))
#define TWO_OVER_PI 0.6366197723675814f
#define HALF_PI     1.5707963267948966f

// fast atan: degree-11 odd minimax on [0,1] + reciprocal range reduction (~1e-5 abs err)
// (metric-neutral: R12/R13 both used this and rel_err stayed 8.198229e-6 exactly)
static __device__ __forceinline__ float fatan(float x) {
    float ax = fabsf(x);
    bool big = ax > 1.0f;
    float z = big ? __fdividef(1.0f, ax) : ax;
    float z2 = z * z;
    float p = -0.0117212f;
    p = fmaf(p, z2,  0.05265332f);
    p = fmaf(p, z2, -0.11643287f);
    p = fmaf(p, z2,  0.19354346f);
    p = fmaf(p, z2, -0.33262347f);
    p = fmaf(p, z2,  0.99997726f);
    float r = z * p;
    r = big ? (HALF_PI - r) : r;
    return copysignf(r, x);
}

__device__ __forceinline__ void covid_deriv(const float y[16], float gam, float pdt,
                                            float aN, float r_dth, float d[16])
{
    float S = y[0], E = y[1], I = y[2];
    float AR = y[3], DHR = y[4], DQR = y[5], AD = y[6], DHD = y[7], DQD = y[8];
    float DVR = y[12], DVD = y[13];
    float inf = aN * gam * S * I;
    float det = C_RD * I;
    float d1m = det * (1.f - pdt);
    float dp  = det * pdt;
    d[0] = -inf;
    d[1] = inf - C_RI * E;
    d[2] = C_RI * E - det;
    d[3] = d1m * 0.8f - C_RRI * AR;
    d[4] = d1m * 0.03f - C_RRH * DHR;
    d[5] = d1m * 0.17f - C_RRI * DQR;
    d[6] = dp * 0.8f - r_dth * AD;
    d[7] = dp * 0.03f - r_dth * DHD;
    d[8] = dp * 0.17f - r_dth * DQD;
    d[9] = C_RRI * (AR + DQR) + C_RRH * DHR;
    d[10] = r_dth * (AD + DQD + DHD);
    d[11] = det * 0.03f;
    d[12] = d1m * 0.0075f - C_RRV * DVR;
    d[13] = dp * 0.0075f - r_dth * DVD;
    d[14] = r_dth * (DHD + DQD);
    d[15] = det * 0.2f;
}
__device__ __forceinline__ float gam_f(float t, float days, float rs20,
                                       float jump, float t_jump, float inv2s2)
{
    float dtj = t - t_jump;
    return TWO_OVER_PI * fatan((days - t) * rs20) + 1.0f + jump * __expf(-dtj * dtj * inv2s2);
}
__device__ __forceinline__ float pdt_f(float t, float pc, float rdd20)
{
    return pc * (fatan(-t * rdd20) + HALF_PI) + 0.001f;
}

__global__ void ode_kernel(const float* __restrict__ pop, const float* __restrict__ ccn,
                           const float* __restrict__ mort, const float* __restrict__ dnn,
                           float* __restrict__ sol)
{
    int b = blockIdx.x * blockDim.x + threadIdx.x;
    if (b >= BATCH) return;
    const float* dn = dnn + (size_t)b * OUTD;
    float alpha = dn[11], days = dn[12], r_s = dn[13], r_dth = dn[14], p_dth = dn[15];
    float r_dthdecay = dn[16], k1 = dn[17], k2 = dn[18], jump = dn[19];
    float t_jump = dn[20], stdn = dn[21];

    float N = pop[b];
    float PopI = ccn[b];
    float PopD = floorf(mort[b] * PopI);
    float R0 = (PopI - PopD > 5.0f * PopD) ? 5.0f * PopD : 0.0f;
    float PopCI = PopI - PopD - R0;
    float ciPD = PopCI / 0.2f;
    float omp = 1.0f - p_dth;

    float y[16];
    y[0] = N - ciPD * (k1 + k2) - R0 / 0.2f - PopD / 0.2f;
    y[1] = ciPD * k1;  y[2] = ciPD * k2;
    y[3] = (ciPD - PopCI) * omp;
    y[4] = PopCI * 0.15f * omp;
    y[5] = PopCI * 0.85f * omp;
    y[6] = (ciPD - PopCI) * p_dth;
    y[7] = PopCI * 0.15f * p_dth;
    y[8] = PopCI * 0.85f * p_dth;
    y[9] = R0 / 0.2f;  y[10] = PopD / 0.2f;
    y[11] = PopCI * 0.15f;
    y[12] = PopCI * 0.0375f * omp;
    y[13] = PopCI * 0.0375f * p_dth;
    y[14] = PopD;  y[15] = PopI;

    float* srow = sol + (size_t)b * TPTS * 16;
#pragma unroll
    for (int i = 0; i < 16; i++) srow[i] = y[i];

    float aN = alpha / N;
    float rs20 = r_s * 0.05f;
    float rdd20 = r_dthdecay * 0.05f;
    float inv2s2 = 1.0f / (2.0f * stdn * stdn);
    float pc = TWO_OVER_PI * (p_dth - 0.001f);

    // endpoint carry: g/p at substep start == previous substep's end (same t expression)
    float gS = gam_f(0.0f, days, rs20, jump, t_jump, inv2s2);
    float pS = pdt_f(0.0f, pc, rdd20);

    for (int seg = 0; seg < TPTS - 1; seg++) {
        float t0 = (float)seg;
        for (int j = 0; j < 10; j++) {
            float t  = t0 + (float)j * 0.1f;
            float tm = t + 0.05f;
            float tn = t0 + (float)(j + 1) * 0.1f;   // == next substep's t (bitwise)
            float g1 = gS, p1 = pS;
            float g2 = gam_f(tm, days, rs20, jump, t_jump, inv2s2);
            float g3 = gam_f(tn, days, rs20, jump, t_jump, inv2s2);
            float p2 = pdt_f(tm, pc, rdd20);
            float p3 = pdt_f(tn, pc, rdd20);
            float k[16], acc[16], yy[16];
            covid_deriv(y, g1, p1, aN, r_dth, k);
#pragma unroll
            for (int i = 0; i < 16; i++) { acc[i] = k[i]; yy[i] = y[i] + 0.05f * k[i]; }
            covid_deriv(yy, g2, p2, aN, r_dth, k);
#pragma unroll
            for (int i = 0; i < 16; i++) { acc[i] += 2.f * k[i]; yy[i] = y[i] + 0.05f * k[i]; }
            covid_deriv(yy, g2, p2, aN, r_dth, k);
#pragma unroll
            for (int i = 0; i < 16; i++) { acc[i] += 2.f * k[i]; yy[i] = y[i] + 0.1f * k[i]; }
            covid_deriv(yy, g3, p3, aN, r_dth, k);
#pragma unroll
            for (int i = 0; i < 16; i++) y[i] += (0.1f / 6.0f) * (acc[i] + k[i]);
            gS = g3; pS = p3;
        }
        float* o = srow + (size_t)(seg + 1) * 16;
#pragma unroll
        for (int i = 0; i < 16; i++) o[i] = y[i];
    }
}

// ============================ launch ============================
static void* sym(const void* s) { void* p; cudaGetSymbolAddress(&p, s); return p; }

extern "C" void kernel_launch(void* const* d_in, const int* in_sizes, int n_in,
                              void* d_out, int out_size)
{
    const float* mi    = (const float*)d_in[0];
    const float* pop   = (const float*)d_in[1];
    const float* ccn   = (const float*)d_in[2];
    const float* mort  = (const float*)d_in[3];
    const float* h0    = (const float*)d_in[4];
    const float* c0    = (const float*)d_in[5];
    const float* W_ih0 = (const float*)d_in[6];
    const float* W_ihR = (const float*)d_in[7];
    const float* W_hh  = (const float*)d_in[8];
    const float* b_ih  = (const float*)d_in[9];
    const float* b_hh  = (const float*)d_in[10];
    const float* mW1   = (const float*)d_in[11];
    const float* mb1   = (const float*)d_in[12];
    const float* mW2   = (const float*)d_in[13];
    const float* mb2   = (const float*)d_in[14];
    const float* rW1   = (const float*)d_in[15];
    const float* rb1   = (const float*)d_in[16];
    const float* rW2   = (const float*)d_in[17];
    const float* rb2   = (const float*)d_in[18];
    const float* rng   = (const float*)d_in[19];
    const void*  scl   = d_in[20];

    float* out = (float*)d_out;
    float* sol = out;
    float* dnn = out + (size_t)BATCH * TPTS * 16;
    float* ts  = dnn + (size_t)BATCH * OUTD;
    float* raw = ts  + (size_t)BATCH * HDIM;

    float* zb    = (float*)sym(g_z);
    float* biasp = (float*)sym(g_biasp);
    bf16 *x30h = (bf16*)sym(g_x30h), *x30l = (bf16*)sym(g_x30l);
    bf16 *mih  = (bf16*)sym(g_mih),  *mil  = (bf16*)sym(g_mil);
    bf16 *wi0h = (bf16*)sym(g_wi0h), *wi0l = (bf16*)sym(g_wi0l);
    bf16 *wirh = (bf16*)sym(g_wirh), *wirl = (bf16*)sym(g_wirl);
    bf16 *whhh = (bf16*)sym(g_whhh), *whhl = (bf16*)sym(g_whhl);
    bf16 *h0h  = (bf16*)sym(g_h0h),  *h0l  = (bf16*)sym(g_h0l);
    bf16 *mw1h = (bf16*)sym(g_mw1h), *mw1l = (bf16*)sym(g_mw1l);
    bf16 *mw2h = (bf16*)sym(g_mw2h), *mw2l = (bf16*)sym(g_mw2l);
    bf16 *r1ah = (bf16*)sym(g_r1ah), *r1al = (bf16*)sym(g_r1al);
    bf16 *r1bh = (bf16*)sym(g_r1bh), *r1bl = (bf16*)sym(g_r1bl);
    bf16 *xAh  = (bf16*)sym(g_xAh),  *xAl  = (bf16*)sym(g_xAl);
    bf16 *xBh  = (bf16*)sym(g_xBh),  *xBl  = (bf16*)sym(g_xBl);
    bf16 *m1h  = (bf16*)sym(g_m1h),  *m1l  = (bf16*)sym(g_m1l);
    bf16 *m2h  = (bf16*)sym(g_m2h),  *m2l  = (bf16*)sym(g_m2l);

    static cudaStream_t s1 = nullptr;
    static cudaEvent_t  evF = nullptr, evJ = nullptr, evC = nullptr;
    if (!s1) {
        cudaStreamCreateWithFlags(&s1, cudaStreamNonBlocking);
        cudaEventCreateWithFlags(&evF, cudaEventDisableTiming);
        cudaEventCreateWithFlags(&evJ, cudaEventDisableTiming);
        cudaEventCreateWithFlags(&evC, cudaEventDisableTiming);
        cudaFuncSetAttribute(gemm_tc, cudaFuncAttributeMaxDynamicSharedMemorySize, GEMM_SMEM);
    }

    auto CV = [&](cudaStream_t st, const float* s, int rows, int Ks, int ld, int Kd,
                  bf16* h, bf16* l, const float* dv, int perm) {
        int n = rows * Kd;
        conv_hl<<<(n + 255) / 256, 256, 0, st>>>(s, rows, Ks, ld, Kd, h, l, dv, perm);
    };
    auto GL = [&](cudaStream_t st, dim3 grid, Seg* sg, int ns, const float* b1,
                  const float* addC, const float* c0p, float* tso,
                  float* Cf, bf16* Ch, bf16* Cl, int ldc, int op) {
        GArgs a = {};
        for (int i = 0; i < ns; i++) a.s[i] = sg[i];
        a.nseg = ns; a.bias1 = b1; a.addC = addC; a.c0 = c0p; a.tso = tso;
        a.Cf = Cf; a.Ch = Ch; a.Cl = Cl; a.ldc = ldc; a.op = op;
        gemm_tc<<<grid, 256, GEMM_SMEM, st>>>(a);
    };

    // fork s1 from capture origin
    cudaEventRecord(evF, 0);
    cudaStreamWaitEvent(s1, evF, 0);

    // ---- default stream: ONLY layer-0-critical conversions ----
    CV(0, mi,    BATCH, TTL,  IN_DIM, 64,   x30h, x30l, pop,     0);
    CV(0, W_ih0, G4,    TTL,  TTL,    64,   wi0h, wi0l, nullptr, 2048);
    CV(0, W_hh,  G4,    HDIM, HDIM,   HDIM, whhh, whhl, nullptr, 2048);
    CV(0, h0,    BATCH, HDIM, HDIM,   HDIM, h0h,  h0l,  nullptr, 0);
    biasp_kernel<<<(NL * G4 + 255) / 256, 256>>>(b_ih, b_hh, biasp);

    // ---- s1: conversions for layers 1-4, meta branch, readout weights,
    //          and the m2-half of the z-GEMM (overlaps the LSTM chain) ----
    CV(s1, W_ihR,                     4 * G4,    HDIM, HDIM, HDIM, wirh, wirl, nullptr, 2048);
    CV(s1, W_hh + (size_t)G4 * HDIM,  4 * G4,    HDIM, HDIM, HDIM,
       whhh + (size_t)G4 * HDIM, whhl + (size_t)G4 * HDIM, nullptr, 2048);
    CV(s1, h0 + (size_t)BATCH * HDIM, 4 * BATCH, HDIM, HDIM, HDIM,
       h0h + (size_t)BATCH * HDIM, h0l + (size_t)BATCH * HDIM, nullptr, 0);
    cudaEventRecord(evC, s1);

    CV(s1, mi + TTL,   BATCH,    30,   IN_DIM, 64,   mih,  mil,  nullptr, 0);
    CV(s1, mW1,        HDIM,     30,   30,     64,   mw1h, mw1l, nullptr, 0);
    CV(s1, mW2,        HDIM,     HDIM, HDIM,   HDIM, mw2h, mw2l, nullptr, 0);
    CV(s1, rW1,        2 * HDIM, HDIM, 2*HDIM, HDIM, r1ah, r1al, nullptr, 0);
    CV(s1, rW1 + HDIM, 2 * HDIM, HDIM, 2*HDIM, HDIM, r1bh, r1bl, nullptr, 0);
    dim3 mGrid(HDIM / 128, BATCH / 128);
    { Seg sg[3] = { {mih, mw1h, 64}, {mil, mw1h, 64}, {mih, mw1l, 64} };
      GL(s1, mGrid, sg, 3, mb1, nullptr, nullptr, nullptr, nullptr, m1h, m1l, HDIM, 1); }
    { Seg sg[3] = { {m1h, mw2h, HDIM}, {m1l, mw2h, HDIM}, {m1h, mw2l, HDIM} };
      GL(s1, mGrid, sg, 3, mb2, nullptr, nullptr, nullptr, nullptr, m2h, m2l, HDIM, 1); }
    // z-GEMM piece A: m2-half -> fp32 partial in zb (includes rb1), overlaps LSTM
    dim3 zGrid(2 * HDIM / 128, BATCH / 128);
    { Seg sg[3] = { {m2h, r1bh, HDIM}, {m2l, r1bh, HDIM}, {m2h, r1bl, HDIM} };
      GL(s1, zGrid, sg, 3, rb1, nullptr, nullptr, nullptr, zb, nullptr, nullptr, 2 * HDIM, 0); }
    cudaEventRecord(evJ, s1);

    // ---- default stream: LSTM chain (128x128 CTAs, 2/SM), fused cell, ping-pong ----
    dim3 gGrid(G4 / 128, BATCH / 128);
    for (int l = 0; l < NL; l++) {
        if (l == 1) cudaStreamWaitEvent(0, evC, 0);
        bf16* ah = (l == 0) ? x30h : ((l & 1) ? xAh : xBh);
        bf16* al = (l == 0) ? x30l : ((l & 1) ? xAl : xBl);
        bf16* oh = (l & 1) ? xBh : xAh;
        bf16* ol = (l & 1) ? xBl : xAl;
        int   Kx = l ? HDIM : 64;
        bf16* wh = l ? (wirh + (size_t)(l - 1) * G4 * HDIM) : wi0h;
        bf16* wl = l ? (wirl + (size_t)(l - 1) * G4 * HDIM) : wi0l;
        bf16* hh = h0h + (size_t)l * BATCH * HDIM;
        bf16* hl = h0l + (size_t)l * BATCH * HDIM;
        bf16* Wh = whhh + (size_t)l * G4 * HDIM;
        bf16* Wl = whhl + (size_t)l * G4 * HDIM;
        Seg sg[6] = { {ah, wh, Kx}, {al, wh, Kx}, {ah, wl, Kx},
                      {hh, Wh, HDIM}, {hl, Wh, HDIM}, {hh, Wl, HDIM} };
        GL(0, gGrid, sg, 6, biasp + (size_t)l * G4, nullptr,
           c0 + (size_t)l * BATCH * HDIM, (l == NL - 1) ? ts : nullptr,
           nullptr, oh, ol, HDIM, 3);
    }
    bf16* xfh = xAh;   // layer 4 (even) wrote buffer A
    bf16* xfl = xAl;

    // join piece A + meta, then z-GEMM piece B: x-half, pre-add zb partial, tanh
    cudaStreamWaitEvent(0, evJ, 0);
    { Seg sg[3] = { {xfh, r1ah, HDIM}, {xfl, r1ah, HDIM}, {xfh, r1al, HDIM} };
      GL(0, zGrid, sg, 3, nullptr, zb, nullptr, nullptr, zb, nullptr, nullptr, 2 * HDIM, 2); }

    raw_dnn_kernel<<<BATCH, 256>>>(zb, rW2, rb2, rng, scl, raw, dnn);
    ode_kernel<<<(BATCH + 63) / 64, 64>>>(pop, ccn, mort, dnn, sol);
}